// round 3
// baseline (speedup 1.0000x reference)
#include <cuda_runtime.h>
#include <math.h>
#include <stdint.h>

#define NB 4
#define NPTS 8192
#define NP 2048
#define NS 32
#define WARPS_PER_BLOCK 16
#define NTHREADS (WARPS_PER_BLOCK * 32)
#define NCH 34
#define CSTRIDE (NP * NS) /* 65536 */
#define EPSF 1e-6f

__device__ __forceinline__ unsigned rotl32(unsigned x, int d) {
    return (x << d) | (x >> (32 - d));
}

// Reproduce jax.random.uniform(jax.random.key(42), (4,1,2048,32)) at flat index
// i, then (u - 0.5) * 2*pi.
// JAX default jax_threefry_partitionable=True:
//   counts = iota(uint64); x0_in = hi32(count) = 0, x1_in = lo32(count) = i,
//   key = (0, 42); 32-bit draw = bits1 ^ bits2  (XOR of the two threefry
//   outputs — see _threefry_random_bits_partitionable in jax/_src/prng.py).
__device__ float jax_rand_angle(unsigned i) {
    const unsigned ks0 = 0u, ks1 = 42u, ks2 = 0u ^ 42u ^ 0x1BD11BDAu;
    unsigned x0 = 0u + ks0;   // hi(count) + ks0
    unsigned x1 = i + ks1;    // lo(count) + ks1
#define TF_RND(r) { x0 += x1; x1 = rotl32(x1, (r)); x1 ^= x0; }
    TF_RND(13) TF_RND(15) TF_RND(26) TF_RND(6)  x0 += ks1; x1 += ks2 + 1u;
    TF_RND(17) TF_RND(29) TF_RND(16) TF_RND(24) x0 += ks2; x1 += ks0 + 2u;
    TF_RND(13) TF_RND(15) TF_RND(26) TF_RND(6)  x0 += ks0; x1 += ks1 + 3u;
    TF_RND(17) TF_RND(29) TF_RND(16) TF_RND(24) x0 += ks1; x1 += ks2 + 4u;
    TF_RND(13) TF_RND(15) TF_RND(26) TF_RND(6)  x0 += ks2; x1 += ks0 + 5u;
#undef TF_RND
    unsigned bits = x0 ^ x1;  // partitionable 32-bit fold: bits1 ^ bits2
    float u = __uint_as_float((bits >> 9) | 0x3F800000u) - 1.0f;
    u = fmaxf(u, 0.0f);
    return (u - 0.5f) * 6.283185307179586f;
}

extern __shared__ float smem_dyn[];

__global__ void __launch_bounds__(NTHREADS, 2)
qgq_kernel(const float* __restrict__ xyz,
           const float* __restrict__ new_xyz,
           float* __restrict__ out)
{
    float* sx = smem_dyn;            // [NPTS]
    float* sy = smem_dyn + NPTS;     // [NPTS]
    float* sz = smem_dyn + 2 * NPTS; // [NPTS]
    float* angbuf = smem_dyn + 3 * NPTS;                    // [WARPS*32]
    int*   idxbuf = (int*)(smem_dyn + 3 * NPTS + WARPS_PER_BLOCK * 32); // [WARPS*32]

    const int warp = threadIdx.x >> 5;
    const int lane = threadIdx.x & 31;
    const int g = blockIdx.x * WARPS_PER_BLOCK + warp; // group id in [0, B*P)
    const int b = g >> 11;  // / NP
    const int p = g & (NP - 1);

    // ---- stage this batch's xyz into SMEM as SoA (coalesced GMEM reads) ----
    const float* xb = xyz + (size_t)b * NPTS * 3;
    for (int j = threadIdx.x; j < NPTS * 3; j += NTHREADS) {
        float v = xb[j];
        int i = j / 3;
        int c = j - i * 3;
        smem_dyn[c * NPTS + i] = v;
    }
    __syncthreads();

    float* myang = angbuf + warp * 32;
    int*   myidx = idxbuf + warp * 32;

    const float cx = new_xyz[((size_t)b * NP + p) * 3 + 0];
    const float cy = new_xyz[((size_t)b * NP + p) * 3 + 1];
    const float cz = new_xyz[((size_t)b * NP + p) * 3 + 2];

    // ---- ball query: first NS smallest-index points with d2 < R^2 ----
    const float R2 = (float)(0.2 * 0.2);
    int found = 0;
    const unsigned ltmask = (1u << lane) - 1u;
    for (int base = 0; base < NPTS; base += 32) {
        int i = base + lane;
        float dx = __fadd_rn(cx, -sx[i]);
        float dy = __fadd_rn(cy, -sy[i]);
        float dz = __fadd_rn(cz, -sz[i]);
        float d2 = __fadd_rn(__fadd_rn(__fmul_rn(dx, dx), __fmul_rn(dy, dy)),
                             __fmul_rn(dz, dz));
        bool hit = d2 < R2;
        unsigned m = __ballot_sync(0xFFFFFFFFu, hit);
        if (hit) {
            int pos = found + __popc(m & ltmask);
            if (pos < NS) myidx[pos] = i;
        }
        found += __popc(m);
        if (found >= NS) break;
    }
    __syncwarp();
    int cnt = min(found, NS);
    int nb0 = (cnt > 0) ? myidx[0] : 0;
    int nb  = (lane < cnt) ? myidx[lane] : nb0;

    // rel = grouped point - center
    float rx = __fadd_rn(sx[nb], -cx);
    float ry = __fadd_rn(sy[nb], -cy);
    float rz = __fadd_rn(sz[nb], -cz);

    // ---- p1 = normalize(center) (warp-uniform) ----
    float cn = sqrtf(cx * cx + cy * cy + cz * cz);
    float den1 = cn + EPSF;
    float px = __fdiv_rn(cx, den1);
    float py = __fdiv_rn(cy, den1);
    float pz = __fdiv_rn(cz, den1);

    // ---- _project_one: second normalize of p, then reference vector ----
    float pn = sqrtf(px * px + py * py + pz * pz);
    float den2 = pn + EPSF;
    float p2x = __fdiv_rn(px, den2);
    float p2y = __fdiv_rn(py, den2);
    float p2z = __fdiv_rn(pz, den2);
    bool colin = fabsf(p2x) > 0.999f;
    float rfx = colin ? (-p2y * p2x) : (1.0f - p2x * p2x);
    float rfy = colin ? (1.0f - p2y * p2y) : (-p2x * p2y);
    float rfz = colin ? (-p2y * p2z) : (-p2x * p2z);
    float rn = sqrtf(rfx * rfx + rfy * rfy + rfz * rfz);
    float den3 = rn + EPSF;
    float ix = __fdiv_rn(rfx, den3);
    float iy = __fdiv_rn(rfy, den3);
    float iz = __fdiv_rn(rfz, den3);

    // ---- per-lane: project rel onto plane orthogonal to p1, get angle ----
    float dotp = px * rx + py * ry + pz * rz;
    float vx = rx - dotp * px;
    float vy = ry - dotp * py;
    float vz = rz - dotp * pz;
    float vn = sqrtf(vx * vx + vy * vy + vz * vz);
    float den4 = vn + EPSF;
    float qx = __fdiv_rn(vx, den4);
    float qy = __fdiv_rn(vy, den4);
    float qz = __fdiv_rn(vz, den4);
    float pr2 = qx * qx + qy * qy + qz * qz;
    float sinv = (iy * qz - iz * qy) * px + (iz * qx - ix * qz) * py +
                 (ix * qy - iy * qx) * pz;
    float cosv = ix * qx + iy * qy + iz * qz;
    float ang = atan2f(sinv, cosv);
    if (pr2 < 1e-12f) {
        ang = jax_rand_angle(((unsigned)(b * NP + p)) * NS + (unsigned)lane);
    }

    // ---- stable argsort by angle (tie-break by original index) ----
    myang[lane] = ang;
    __syncwarp();
    int rank = 0;
#pragma unroll
    for (int t = 0; t < 32; t++) {
        float a = myang[t];
        rank += ((a < ang) || (a == ang && t < lane)) ? 1 : 0;
    }
    __syncwarp();
    myidx[rank] = lane;
    __syncwarp();
    int src = myidx[lane];
    rx = __shfl_sync(0xFFFFFFFFu, rx, src);
    ry = __shfl_sync(0xFFFFFFFFu, ry, src);
    rz = __shfl_sync(0xFFFFFFFFu, rz, src);

    // ---- invariance features on sorted rel ----
    float d2s = rx * rx + ry * ry + rz * rz;
    float norm2 = sqrtf(d2s + 1e-12f);
    float cosang = __fdiv_rn(px * rx + py * ry + pz * rz, norm2);
    cosang = fminf(fmaxf(cosang, -1.0f + EPSF), 1.0f - EPSF);
    float angle = acosf(cosang);

    // ---- quaternion on sorted rel ----
    float dist = sqrtf(d2s);
    float den5 = dist + EPSF;
    float theta = __fmul_rn(__fdiv_rn(dist, 0.2f), 1.5707963267948966f);
    float q0 = cosf(theta);
    float st = sinf(theta);
    float q1 = st * __fdiv_rn(rx, den5);
    float q2 = st * __fdiv_rn(ry, den5);
    float q3 = st * __fdiv_rn(rz, den5);

    // ---- write output: (B, 34, P, 32), lane-contiguous along last axis ----
    float* ob = out + (size_t)b * NCH * CSTRIDE + (size_t)p * NS + lane;
    ob[0] = norm2;
    ob[(size_t)CSTRIDE] = angle;
    float q[4] = {q0, q1, q2, q3};
#pragma unroll
    for (int c = 0; c < 4; c++) {
#pragma unroll
        for (int m = 0; m < 8; m++) {
            float v = __shfl_sync(0xFFFFFFFFu, q[c], (lane + m) & 31);
            ob[(size_t)(2 + c * 8 + m) * CSTRIDE] = v;
        }
    }
}

extern "C" void kernel_launch(void* const* d_in, const int* in_sizes, int n_in,
                              void* d_out, int out_size) {
    const float* xyz = (const float*)d_in[0];
    const float* new_xyz = (const float*)d_in[1];
    // d_in[2] (fps_idx) is not needed: new_xyz == xyz[fps_idx] and the
    // prepended fps column is dropped by the reference before use.
    float* out = (float*)d_out;

    const int smem_bytes =
        (3 * NPTS + WARPS_PER_BLOCK * 32) * (int)sizeof(float) +
        WARPS_PER_BLOCK * 32 * (int)sizeof(int);
    cudaFuncSetAttribute(qgq_kernel,
                         cudaFuncAttributeMaxDynamicSharedMemorySize,
                         smem_bytes);
    const int nblocks = (NB * NP) / WARPS_PER_BLOCK; // 512
    qgq_kernel<<<nblocks, NTHREADS, smem_bytes>>>(xyz, new_xyz, out);
}

// round 4
// speedup vs baseline: 1.2796x; 1.2796x over previous
#include <cuda_runtime.h>
#include <math.h>
#include <stdint.h>

#define NB 4
#define NPTS 8192
#define NP 2048
#define NS 32
#define WARPS_PER_BLOCK 32
#define NTHREADS (WARPS_PER_BLOCK * 32)
#define NCH 34
#define CSTRIDE (NP * NS) /* 65536 */
#define EPSF 1e-6f

__device__ __forceinline__ unsigned rotl32(unsigned x, int d) {
    return (x << d) | (x >> (32 - d));
}

// Reproduce jax.random.uniform(jax.random.key(42), (4,1,2048,32)) at flat index
// i, then (u - 0.5) * 2*pi.  (threefry2x32 partitionable: x0=hi(count)=0,
// x1=lo(count)=i, key=(0,42), 32-bit draw = out0 ^ out1.)
__device__ float jax_rand_angle(unsigned i) {
    const unsigned ks0 = 0u, ks1 = 42u, ks2 = 0u ^ 42u ^ 0x1BD11BDAu;
    unsigned x0 = 0u + ks0;
    unsigned x1 = i + ks1;
#define TF_RND(r) { x0 += x1; x1 = rotl32(x1, (r)); x1 ^= x0; }
    TF_RND(13) TF_RND(15) TF_RND(26) TF_RND(6)  x0 += ks1; x1 += ks2 + 1u;
    TF_RND(17) TF_RND(29) TF_RND(16) TF_RND(24) x0 += ks2; x1 += ks0 + 2u;
    TF_RND(13) TF_RND(15) TF_RND(26) TF_RND(6)  x0 += ks0; x1 += ks1 + 3u;
    TF_RND(17) TF_RND(29) TF_RND(16) TF_RND(24) x0 += ks1; x1 += ks2 + 4u;
    TF_RND(13) TF_RND(15) TF_RND(26) TF_RND(6)  x0 += ks2; x1 += ks0 + 5u;
#undef TF_RND
    unsigned bits = x0 ^ x1;
    float u = __uint_as_float((bits >> 9) | 0x3F800000u) - 1.0f;
    u = fmaxf(u, 0.0f);
    return (u - 0.5f) * 6.283185307179586f;
}

extern __shared__ float smem_dyn[];

__global__ void __launch_bounds__(NTHREADS, 2)
qgq_kernel(const float* __restrict__ xyz,
           const float* __restrict__ new_xyz,
           float* __restrict__ out)
{
    // smem layout: float2 sxy[NPTS] | float sz[NPTS] | ang[W*32] | idx[W*32]
    float2* sxy = (float2*)smem_dyn;                     // 64 KB
    float*  sz  = smem_dyn + 2 * NPTS;                   // 32 KB
    float*  angbuf = smem_dyn + 3 * NPTS;                // 4 KB
    int*    idxbuf = (int*)(smem_dyn + 3 * NPTS + WARPS_PER_BLOCK * 32);

    const int warp = threadIdx.x >> 5;
    const int lane = threadIdx.x & 31;
    const int g = blockIdx.x * WARPS_PER_BLOCK + warp; // group id in [0, B*P)
    const int b = g >> 11;  // / NP
    const int p = g & (NP - 1);

    // ---- stage this batch's xyz into SMEM (packed float2 + float) ----
    const float* xb = xyz + (size_t)b * NPTS * 3;
    for (int i = threadIdx.x; i < NPTS; i += NTHREADS) {
        float x = xb[3 * i + 0];
        float y = xb[3 * i + 1];
        float z = xb[3 * i + 2];
        sxy[i] = make_float2(x, y);
        sz[i] = z;
    }
    __syncthreads();

    float* myang = angbuf + warp * 32;
    int*   myidx = idxbuf + warp * 32;

    const float cx = new_xyz[((size_t)b * NP + p) * 3 + 0];
    const float cy = new_xyz[((size_t)b * NP + p) * 3 + 1];
    const float cz = new_xyz[((size_t)b * NP + p) * 3 + 2];

    // ---- ball query: first NS smallest-index points with d2 < R^2 ----
    // 4-way unrolled: evaluate 128 points per super-iteration for ILP.
    const float R2 = (float)(0.2 * 0.2);
    int found = 0;
    const unsigned ltmask = (1u << lane) - 1u;
    for (int base = 0; base < NPTS; base += 128) {
        float d2v[4];
#pragma unroll
        for (int c = 0; c < 4; c++) {
            int i = base + c * 32 + lane;
            float2 v = sxy[i];
            float z = sz[i];
            float dx = __fadd_rn(cx, -v.x);
            float dy = __fadd_rn(cy, -v.y);
            float dz = __fadd_rn(cz, -z);
            d2v[c] = __fadd_rn(
                __fadd_rn(__fmul_rn(dx, dx), __fmul_rn(dy, dy)),
                __fmul_rn(dz, dz));
        }
        unsigned mm[4];
#pragma unroll
        for (int c = 0; c < 4; c++)
            mm[c] = __ballot_sync(0xFFFFFFFFu, d2v[c] < R2);
#pragma unroll
        for (int c = 0; c < 4; c++) {
            unsigned m = mm[c];
            if ((m >> lane) & 1u) {
                int pos = found + __popc(m & ltmask);
                if (pos < NS) myidx[pos] = base + c * 32 + lane;
            }
            found += __popc(m);
        }
        if (found >= NS) break;
    }
    __syncwarp();
    int cnt = min(found, NS);
    int nb0 = (cnt > 0) ? myidx[0] : 0;
    int nb  = (lane < cnt) ? myidx[lane] : nb0;

    // rel = grouped point - center
    float2 nbxy = sxy[nb];
    float rx = __fadd_rn(nbxy.x, -cx);
    float ry = __fadd_rn(nbxy.y, -cy);
    float rz = __fadd_rn(sz[nb], -cz);

    // ---- p1 = normalize(center) (warp-uniform) ----
    float cn = sqrtf(cx * cx + cy * cy + cz * cz);
    float den1 = cn + EPSF;
    float px = __fdiv_rn(cx, den1);
    float py = __fdiv_rn(cy, den1);
    float pz = __fdiv_rn(cz, den1);

    // ---- _project_one: second normalize of p, then reference vector ----
    float pn = sqrtf(px * px + py * py + pz * pz);
    float den2 = pn + EPSF;
    float p2x = __fdiv_rn(px, den2);
    float p2y = __fdiv_rn(py, den2);
    float p2z = __fdiv_rn(pz, den2);
    bool colin = fabsf(p2x) > 0.999f;
    float rfx = colin ? (-p2y * p2x) : (1.0f - p2x * p2x);
    float rfy = colin ? (1.0f - p2y * p2y) : (-p2x * p2y);
    float rfz = colin ? (-p2y * p2z) : (-p2x * p2z);
    float rn = sqrtf(rfx * rfx + rfy * rfy + rfz * rfz);
    float den3 = rn + EPSF;
    float ix = __fdiv_rn(rfx, den3);
    float iy = __fdiv_rn(rfy, den3);
    float iz = __fdiv_rn(rfz, den3);

    // ---- per-lane: project rel onto plane orthogonal to p1, get angle ----
    float dotp = px * rx + py * ry + pz * rz;
    float vx = rx - dotp * px;
    float vy = ry - dotp * py;
    float vz = rz - dotp * pz;
    float vn = sqrtf(vx * vx + vy * vy + vz * vz);
    float den4 = vn + EPSF;
    float qx = __fdiv_rn(vx, den4);
    float qy = __fdiv_rn(vy, den4);
    float qz = __fdiv_rn(vz, den4);
    float pr2 = qx * qx + qy * qy + qz * qz;
    float sinv = (iy * qz - iz * qy) * px + (iz * qx - ix * qz) * py +
                 (ix * qy - iy * qx) * pz;
    float cosv = ix * qx + iy * qy + iz * qz;
    float ang = atan2f(sinv, cosv);
    if (pr2 < 1e-12f) {
        ang = jax_rand_angle(((unsigned)(b * NP + p)) * NS + (unsigned)lane);
    }

    // ---- stable argsort by angle (tie-break by original index) ----
    myang[lane] = ang;
    __syncwarp();
    int rank = 0;
#pragma unroll
    for (int t = 0; t < 32; t++) {
        float a = myang[t];
        rank += ((a < ang) || (a == ang && t < lane)) ? 1 : 0;
    }
    __syncwarp();
    myidx[rank] = lane;
    __syncwarp();
    int src = myidx[lane];
    rx = __shfl_sync(0xFFFFFFFFu, rx, src);
    ry = __shfl_sync(0xFFFFFFFFu, ry, src);
    rz = __shfl_sync(0xFFFFFFFFu, rz, src);

    // ---- invariance features on sorted rel ----
    float d2s = rx * rx + ry * ry + rz * rz;
    float norm2 = sqrtf(d2s + 1e-12f);
    float cosang = __fdiv_rn(px * rx + py * ry + pz * rz, norm2);
    cosang = fminf(fmaxf(cosang, -1.0f + EPSF), 1.0f - EPSF);
    float angle = acosf(cosang);

    // ---- quaternion on sorted rel ----
    float dist = sqrtf(d2s);
    float den5 = dist + EPSF;
    float theta = __fmul_rn(__fdiv_rn(dist, 0.2f), 1.5707963267948966f);
    float q0 = cosf(theta);
    float st = sinf(theta);
    float q1 = st * __fdiv_rn(rx, den5);
    float q2 = st * __fdiv_rn(ry, den5);
    float q3 = st * __fdiv_rn(rz, den5);

    // ---- write output: (B, 34, P, 32), lane-contiguous along last axis ----
    float* ob = out + (size_t)b * NCH * CSTRIDE + (size_t)p * NS + lane;
    ob[0] = norm2;
    ob[(size_t)CSTRIDE] = angle;
    float q[4] = {q0, q1, q2, q3};
#pragma unroll
    for (int c = 0; c < 4; c++) {
#pragma unroll
        for (int m = 0; m < 8; m++) {
            float v = __shfl_sync(0xFFFFFFFFu, q[c], (lane + m) & 31);
            ob[(size_t)(2 + c * 8 + m) * CSTRIDE] = v;
        }
    }
}

extern "C" void kernel_launch(void* const* d_in, const int* in_sizes, int n_in,
                              void* d_out, int out_size) {
    const float* xyz = (const float*)d_in[0];
    const float* new_xyz = (const float*)d_in[1];
    // d_in[2] (fps_idx) unused: new_xyz == xyz[fps_idx], fps column dropped.
    float* out = (float*)d_out;

    const int smem_bytes =
        (3 * NPTS + WARPS_PER_BLOCK * 32) * (int)sizeof(float) +
        WARPS_PER_BLOCK * 32 * (int)sizeof(int);
    cudaFuncSetAttribute(qgq_kernel,
                         cudaFuncAttributeMaxDynamicSharedMemorySize,
                         smem_bytes);
    const int nblocks = (NB * NP) / WARPS_PER_BLOCK; // 256 — single wave
    qgq_kernel<<<nblocks, NTHREADS, smem_bytes>>>(xyz, new_xyz, out);
}